// round 4
// baseline (speedup 1.0000x reference)
#include <cuda_runtime.h>
#include <cstdint>

#define B_    2
#define NH_   8
#define N_    4096
#define D_    64
#define K2_   49
#define DH_   32           // D per CTA (half-row split)
#define VH_F4 392          // DH_*K2_/4 = 1568/4
#define THREADS 128
#define ROWS  8            // rows per CTA

__device__ __forceinline__ uint32_t smem_u32(const void* p) {
    return (uint32_t)__cvta_generic_to_shared(p);
}
__device__ __forceinline__ void cp16(uint32_t dst, const void* src) {
    asm volatile("cp.async.cg.shared.global [%0], [%1], 16;\n" :: "r"(dst), "l"(src));
}
__device__ __forceinline__ void cp4(uint32_t dst, const void* src) {
    asm volatile("cp.async.ca.shared.global [%0], [%1], 4;\n" :: "r"(dst), "l"(src));
}
__device__ __forceinline__ void cp_commit() {
    asm volatile("cp.async.commit_group;\n" ::: "memory");
}
template <int NPend>
__device__ __forceinline__ void cp_wait() {
    asm volatile("cp.async.wait_group %0;\n" :: "n"(NPend) : "memory");
}

struct __align__(16) Stage {
    float4 v[VH_F4];       // 6272 B  (half of the row's v tile)
    float  q[D_];          // 256 B   (full q; attn needs all of D)
    float  al[K2_];        // 196 B
    float  b[K2_];         // 196 B
    float  pad[2];         // sizeof = 6928, 16B multiple
};

__global__ __launch_bounds__(THREADS, 16)
void sw_attention_av_split(const float* __restrict__ q_norm,      // [B,NH,N,D]
                           const float* __restrict__ attn_local,  // [B,NH,N,K2]
                           const float* __restrict__ v_local,     // [B,NH,N,D,K2]
                           const float* __restrict__ tokens,      // [NH,D,K2]
                           const float* __restrict__ bias,        // [NH,N,K2]
                           float* __restrict__ out)               // [B,NH,N,D]
{
    __shared__ Stage st[2];
    __shared__ float s_attn[K2_ + 1];    // [49] = 0 pad

    const int t    = threadIdx.x;
    const int half = blockIdx.x & 1;                 // which 32 d-values
    const int row0 = (blockIdx.x >> 1) * ROWS;
    const int h    = (row0 >> 12) & (NH_ - 1);
    const float* tok_h = tokens + h * (D_ * K2_);

    auto prefetch = [&](int s, int row) {
        // half-row of v: floats [row*3136 + half*1568, +1568) => float4 base:
        const float4* vrow = reinterpret_cast<const float4*>(v_local)
                             + (size_t)row * (2 * VH_F4) + (size_t)half * VH_F4;
        uint32_t vdst = smem_u32(st[s].v);
#pragma unroll
        for (int i = 0; i < 3; i++)
            cp16(vdst + (uint32_t)(t + THREADS * i) * 16u, vrow + t + THREADS * i);
        if (t < VH_F4 - 3 * THREADS)                 // 392-384 = 8 leftover
            cp16(vdst + (uint32_t)(t + 3 * THREADS) * 16u, vrow + t + 3 * THREADS);

        if (t < D_ / 4)
            cp16(smem_u32(st[s].q) + (uint32_t)t * 16u,
                 reinterpret_cast<const float4*>(q_norm + (size_t)row * D_) + t);

        if (t < K2_) {
            const int n = row & (N_ - 1);
            cp4(smem_u32(st[s].al) + (uint32_t)t * 4u, attn_local + (size_t)row * K2_ + t);
            cp4(smem_u32(st[s].b)  + (uint32_t)t * 4u, bias + ((size_t)h * N_ + n) * K2_ + t);
        }
        cp_commit();
    };

    if (t == 0) s_attn[K2_] = 0.f;

    prefetch(0, row0);

    for (int r = 0; r < ROWS; r++) {
        if (r + 1 < ROWS) { prefetch((r + 1) & 1, row0 + r + 1); cp_wait<1>(); }
        else              cp_wait<0>();
        __syncthreads();                             // stage r&1 ready

        const Stage& S = st[r & 1];

        // ---- phase 1: attn[k] = q . tokens[:,k] + bias + attn_local
        // 49 threads, 4 accumulators to break the FMA chain; tokens L1-hot.
        if (t < K2_) {
            const float* tk = tok_h + t;
            float a0 = 0.f, a1 = 0.f, a2 = 0.f, a3 = 0.f;
#pragma unroll
            for (int d = 0; d < D_; d += 4) {
                a0 = fmaf(S.q[d + 0], __ldg(tk + (d + 0) * K2_), a0);
                a1 = fmaf(S.q[d + 1], __ldg(tk + (d + 1) * K2_), a1);
                a2 = fmaf(S.q[d + 2], __ldg(tk + (d + 2) * K2_), a2);
                a3 = fmaf(S.q[d + 3], __ldg(tk + (d + 3) * K2_), a3);
            }
            s_attn[t] = (a0 + a1) + (a2 + a3) + S.b[t] + S.al[t];
        }
        __syncthreads();                             // s_attn ready

        // ---- phase 2: out[d] = sum_k attn[k] * v_half[d,k]
        // 64 threads, 2 per d (25/24 split; s_attn[49]==0 makes tail exact).
        if (t < 2 * DH_) {
            const int dl    = t >> 1;                // 0..31
            const int start = (t & 1) * 25;          // 0 or 25
            const float* vd = reinterpret_cast<const float*>(S.v) + dl * K2_ + start;
            const float* ak = s_attn + start;
            float acc = 0.f;
#pragma unroll
            for (int j = 0; j < 25; j++)             // start=25,j=24 -> attn[49]=0
                acc = fmaf(ak[j], vd[j], acc);
            acc += __shfl_xor_sync(0xFFFFFFFFu, acc, 1);
            if (!(t & 1))
                __stcs(out + (size_t)(row0 + r) * D_ + half * DH_ + dl, acc);
        }
        __syncthreads();                             // stage readers done
    }
}

extern "C" void kernel_launch(void* const* d_in, const int* in_sizes, int n_in,
                              void* d_out, int out_size)
{
    const float* q_norm     = (const float*)d_in[0];
    const float* attn_local = (const float*)d_in[1];
    const float* v_local    = (const float*)d_in[2];
    const float* tokens     = (const float*)d_in[3];
    const float* bias       = (const float*)d_in[4];
    float* out = (float*)d_out;

    const int blocks = (B_ * NH_ * N_) / ROWS * 2;   // 16384
    sw_attention_av_split<<<blocks, THREADS>>>(q_norm, attn_local, v_local,
                                               tokens, bias, out);
}

// round 5
// speedup vs baseline: 1.7164x; 1.7164x over previous
#include <cuda_runtime.h>
#include <cstdint>

// Problem constants (fixed by the dataset)
#define B_    2
#define NH_   8
#define N_    4096
#define D_    64
#define K2_   49
#define V_F4  784          // D*K2 floats / 4 = 3136/4
#define THREADS 128
#define ROWS  8            // rows per CTA (8 | 4096 so h is constant per CTA)

__device__ __forceinline__ uint32_t smem_u32(const void* p) {
    return (uint32_t)__cvta_generic_to_shared(p);
}
__device__ __forceinline__ void cp16(uint32_t dst, const void* src) {
    // .cg => L2 only; v_local is streaming (zero reuse), keep L1 for tokens
    asm volatile("cp.async.cg.shared.global [%0], [%1], 16;\n" :: "r"(dst), "l"(src));
}
__device__ __forceinline__ void cp4(uint32_t dst, const void* src) {
    asm volatile("cp.async.ca.shared.global [%0], [%1], 4;\n" :: "r"(dst), "l"(src));
}
__device__ __forceinline__ void cp_commit() {
    asm volatile("cp.async.commit_group;\n" ::: "memory");
}
template <int NPend>
__device__ __forceinline__ void cp_wait() {
    asm volatile("cp.async.wait_group %0;\n" :: "n"(NPend) : "memory");
}

struct __align__(16) Stage {
    float4 v[V_F4];        // 12544 B
    float  q[D_];          // 256 B
    float  al[K2_];        // 196 B
    float  b[K2_];         // 196 B
    float  pad[2];         // keep 16B alignment of array of Stage
};

__global__ __launch_bounds__(THREADS, 8)   // cap regs at 64 -> 8 CTAs/SM
void sw_attention_av_pipe(const float* __restrict__ q_norm,      // [B,NH,N,D]
                          const float* __restrict__ attn_local,  // [B,NH,N,K2]
                          const float* __restrict__ v_local,     // [B,NH,N,D,K2]
                          const float* __restrict__ tokens,      // [NH,D,K2]
                          const float* __restrict__ bias,        // [NH,N,K2]
                          float* __restrict__ out)               // [B,NH,N,D]
{
    __shared__ Stage st[2];
    __shared__ float s_attn[K2_];

    const int t    = threadIdx.x;
    const int row0 = blockIdx.x * ROWS;
    const int h    = (row0 >> 12) & (NH_ - 1);
    const float* tok_h = tokens + h * (D_ * K2_);

    // ---- producer: stage a full row (v + q + attn_local + bias) via cp.async
    auto prefetch = [&](int s, int row) {
        const float4* vrow = reinterpret_cast<const float4*>(v_local) + (size_t)row * V_F4;
        uint32_t vdst = smem_u32(st[s].v);
#pragma unroll
        for (int i = 0; i < 6; i++)
            cp16(vdst + (uint32_t)(t + THREADS * i) * 16u, vrow + t + THREADS * i);
        if (t < V_F4 - 6 * THREADS)                         // 16 leftover float4
            cp16(vdst + (uint32_t)(t + 6 * THREADS) * 16u, vrow + t + 6 * THREADS);

        if (t < D_ / 4)
            cp16(smem_u32(st[s].q) + (uint32_t)t * 16u,
                 reinterpret_cast<const float4*>(q_norm + (size_t)row * D_) + t);

        if (t < K2_) {
            const int n = row & (N_ - 1);
            cp4(smem_u32(st[s].al) + (uint32_t)t * 4u, attn_local + (size_t)row * K2_ + t);
            cp4(smem_u32(st[s].b)  + (uint32_t)t * 4u, bias + ((size_t)h * N_ + n) * K2_ + t);
        }
        cp_commit();
    };

    prefetch(0, row0);

    for (int r = 0; r < ROWS; r++) {
        if (r + 1 < ROWS) {
            prefetch((r + 1) & 1, row0 + r + 1);   // keep the DRAM stream flowing
            cp_wait<1>();                           // stage r's group is complete
        } else {
            cp_wait<0>();
        }
        __syncthreads();

        const Stage& S = st[r & 1];

        // ---- attn[k] = q . tokens[:,k] + bias + attn_local   (tokens: L1-hot)
        if (t < K2_) {
            const float* tk = tok_h + t;
            float a0 = 0.f, a1 = 0.f;
#pragma unroll
            for (int d = 0; d < D_; d += 2) {
                a0 = fmaf(S.q[d + 0], __ldg(tk + (d + 0) * K2_), a0);
                a1 = fmaf(S.q[d + 1], __ldg(tk + (d + 1) * K2_), a1);
            }
            s_attn[t] = a0 + a1 + S.b[t] + S.al[t];
        }
        __syncthreads();

        // ---- out[d] = sum_k attn[k] * v[d,k]   (stride-49 smem: conflict-free)
        if (t < D_) {
            const float* vd = reinterpret_cast<const float*>(S.v) + t * K2_;
            float acc0 = 0.f, acc1 = 0.f;
#pragma unroll
            for (int k = 0; k < 48; k += 2) {
                acc0 = fmaf(s_attn[k + 0], vd[k + 0], acc0);
                acc1 = fmaf(s_attn[k + 1], vd[k + 1], acc1);
            }
            acc0 = fmaf(s_attn[48], vd[48], acc0);
            __stcs(out + (size_t)(row0 + r) * D_ + t, acc0 + acc1);
        }

        // readers of stage (r&1) must finish before iteration r+1 overwrites it
        __syncthreads();
    }
}

extern "C" void kernel_launch(void* const* d_in, const int* in_sizes, int n_in,
                              void* d_out, int out_size)
{
    const float* q_norm     = (const float*)d_in[0];
    const float* attn_local = (const float*)d_in[1];
    const float* v_local    = (const float*)d_in[2];
    const float* tokens     = (const float*)d_in[3];
    const float* bias       = (const float*)d_in[4];
    float* out = (float*)d_out;

    const int blocks = (B_ * NH_ * N_) / ROWS;   // 8192
    sw_attention_av_pipe<<<blocks, THREADS>>>(q_norm, attn_local, v_local,
                                              tokens, bias, out);
}